// round 1
// baseline (speedup 1.0000x reference)
#include <cuda_runtime.h>

// Vanilla tanh RNN: B=4096, T=2048, I=4, H=20, O=4.
// Strategy: thread = (batch, hidden-pair). h exchanged per step through SMEM in a
// DUPLICATED layout ([h_j, h_j]) so the 20x20 recurrent matvec is pure fma.rn.f32x2
// (packed fp32, 2x FFMA throughput on sm_103a). One __syncthreads per step with
// ping-pong double buffering. tanh = 1 - 2/(exp(2x)+1) via ex2.approx + rcp.approx.

#define B_TOTAL 4096
#define T_STEPS 2048
#define I_DIM   4
#define H_DIM   20
#define O_DIM   4
#define P_THR   10          // threads per batch (each owns 2 hidden units)
#define NB      28          // batches per CTA
#define CTA_THREADS 288     // 28*10 = 280, padded to 9 warps
#define NBLK    147         // ceil(4096/28) -> one CTA per SM
#define HSTRIDE 44          // padded per-batch stride (words) in dup SMEM layout

typedef unsigned long long u64;

__device__ __forceinline__ u64 pack2(float lo, float hi) {
    u64 r; asm("mov.b64 %0, {%1,%2};" : "=l"(r) : "f"(lo), "f"(hi)); return r;
}
__device__ __forceinline__ void unpack2(u64 v, float& lo, float& hi) {
    asm("mov.b64 {%0,%1}, %2;" : "=f"(lo), "=f"(hi) : "l"(v));
}
__device__ __forceinline__ u64 fma2(u64 a, u64 b, u64 c) {
    u64 d; asm("fma.rn.f32x2 %0, %1, %2, %3;" : "=l"(d) : "l"(a), "l"(b), "l"(c)); return d;
}
__device__ __forceinline__ u64 add2(u64 a, u64 b) {
    u64 d; asm("add.rn.f32x2 %0, %1, %2;" : "=l"(d) : "l"(a), "l"(b)); return d;
}
__device__ __forceinline__ float ex2a(float x) {
    float r; asm("ex2.approx.f32 %0, %1;" : "=f"(r) : "f"(x)); return r;
}
__device__ __forceinline__ float rcpa(float x) {
    float r; asm("rcp.approx.f32 %0, %1;" : "=f"(r) : "f"(x)); return r;
}

__device__ __forceinline__ void rnn_step(
    const float* __restrict__ src, float* __restrict__ dst,
    int lbc, int p, bool wr, float4 xv,
    const u64* __restrict__ Wp, const u64* __restrict__ Wi, u64 bias2)
{
    const ulonglong2* hv = reinterpret_cast<const ulonglong2*>(src + lbc * HSTRIDE);
    u64 hd[H_DIM];
    #pragma unroll
    for (int q = 0; q < H_DIM / 2; q++) {
        ulonglong2 v = hv[q];           // LDS.128: {h_{2q},h_{2q},h_{2q+1},h_{2q+1}}
        hd[2 * q]     = v.x;            // {h_{2q},   h_{2q}}
        hd[2 * q + 1] = v.y;            // {h_{2q+1}, h_{2q+1}}
    }

    // Two accumulation chains (ILP), seeded with bias and input projection.
    u64 acc_a = fma2(pack2(xv.x, xv.x), Wi[0], bias2);
    acc_a     = fma2(pack2(xv.z, xv.z), Wi[2], acc_a);
    u64 acc_b = fma2(pack2(xv.y, xv.y), Wi[1], pack2(0.f, 0.f));
    acc_b     = fma2(pack2(xv.w, xv.w), Wi[3], acc_b);

    #pragma unroll
    for (int j = 0; j < H_DIM; j += 2) {
        acc_a = fma2(hd[j],     Wp[j],     acc_a);
        acc_b = fma2(hd[j + 1], Wp[j + 1], acc_b);
    }
    u64 acc = add2(acc_a, acc_b);

    float p0, p1;
    unpack2(acc, p0, p1);
    const float C = 2.8853900817779268f;     // 2*log2(e)
    float g0 = ex2a(p0 * C);
    float g1 = ex2a(p1 * C);
    float r0 = rcpa(g0 + 1.0f);
    float r1 = rcpa(g1 + 1.0f);
    float h0n = fmaf(r0, -2.0f, 1.0f);       // tanh(p0)
    float h1n = fmaf(r1, -2.0f, 1.0f);       // tanh(p1)

    if (wr) {
        *reinterpret_cast<float4*>(dst + lbc * HSTRIDE + 4 * p) =
            make_float4(h0n, h0n, h1n, h1n);
    }
}

__global__ void __launch_bounds__(CTA_THREADS, 1)
rnn_tanh_kernel(
    const float* __restrict__ x,     const float* __restrict__ h0,
    const float* __restrict__ W_ih,  const float* __restrict__ W_hh,
    const float* __restrict__ b_ih,  const float* __restrict__ b_hh,
    const float* __restrict__ fc_w,  const float* __restrict__ fc_b,
    float* __restrict__ out)
{
    __shared__ float sm[2][NB * HSTRIDE];

    const int tid = threadIdx.x;
    const int lb  = tid / P_THR;
    const int p   = tid - lb * P_THR;        // 0..9 always
    const int b   = blockIdx.x * NB + lb;
    const bool wr = (lb < NB) && (b < B_TOTAL);
    const int lbc = (lb < NB) ? lb : (NB - 1);
    const int bc  = (b < B_TOTAL) ? b : (B_TOTAL - 1);
    const int o0  = 2 * p;                   // 0..18, always valid row index

    // Per-thread weights: pairs over the two owned outputs (o0, o0+1).
    u64 Wp[H_DIM];
    #pragma unroll
    for (int j = 0; j < H_DIM; j++)
        Wp[j] = pack2(__ldg(&W_hh[o0 * H_DIM + j]), __ldg(&W_hh[(o0 + 1) * H_DIM + j]));
    u64 Wi[I_DIM];
    #pragma unroll
    for (int k = 0; k < I_DIM; k++)
        Wi[k] = pack2(__ldg(&W_ih[o0 * I_DIM + k]), __ldg(&W_ih[(o0 + 1) * I_DIM + k]));
    const u64 bias2 = pack2(__ldg(&b_ih[o0])     + __ldg(&b_hh[o0]),
                            __ldg(&b_ih[o0 + 1]) + __ldg(&b_hh[o0 + 1]));

    // Init h into buffer 0 (duplicated layout).
    {
        float v0 = __ldg(&h0[bc * H_DIM + o0]);
        float v1 = __ldg(&h0[bc * H_DIM + o0 + 1]);
        if (wr)
            *reinterpret_cast<float4*>(&sm[0][lbc * HSTRIDE + 4 * p]) =
                make_float4(v0, v0, v1, v1);
    }
    __syncthreads();

    const float4* xp = reinterpret_cast<const float4*>(x) + (size_t)bc * T_STEPS;
    float4 xv = __ldg(&xp[0]);

    for (int t = 0; t < T_STEPS; t += 2) {
        float4 xn1 = __ldg(&xp[t + 1]);                      // prefetch step t+1
        rnn_step(sm[0], sm[1], lbc, p, wr, xv, Wp, Wi, bias2);
        __syncthreads();
        float4 xn2 = (t + 2 < T_STEPS) ? __ldg(&xp[t + 2]) : xn1;  // prefetch t+2
        rnn_step(sm[1], sm[0], lbc, p, wr, xn1, Wp, Wi, bias2);
        __syncthreads();
        xv = xn2;
    }

    // Final hidden state is in buffer 0 (T even). Linear head: threads p<4.
    if (wr && p < O_DIM) {
        const float* hf = &sm[0][lbc * HSTRIDE];
        float acc = __ldg(&fc_b[p]);
        #pragma unroll
        for (int j = 0; j < H_DIM; j++)
            acc = fmaf(hf[2 * j], __ldg(&fc_w[p * H_DIM + j]), acc);
        out[b * O_DIM + p] = acc;
    }
}

extern "C" void kernel_launch(void* const* d_in, const int* in_sizes, int n_in,
                              void* d_out, int out_size)
{
    const float* x    = (const float*)d_in[0];
    const float* h0   = (const float*)d_in[1];
    const float* W_ih = (const float*)d_in[2];
    const float* W_hh = (const float*)d_in[3];
    const float* b_ih = (const float*)d_in[4];
    const float* b_hh = (const float*)d_in[5];
    const float* fc_w = (const float*)d_in[6];
    const float* fc_b = (const float*)d_in[7];
    float* out = (float*)d_out;

    rnn_tanh_kernel<<<NBLK, CTA_THREADS>>>(x, h0, W_ih, W_hh, b_ih, b_hh,
                                           fc_w, fc_b, out);
}

// round 2
// speedup vs baseline: 1.4561x; 1.4561x over previous
#include <cuda_runtime.h>

// Vanilla tanh RNN: B=4096, T=2048, I=4, H=20, O=4.
// Warp-synchronous design: each warp owns 3 batches (10 lanes each, lanes 30/31 idle),
// h exchanged through a warp-private SMEM ping-pong buffer with one __syncwarp per step.
// h stored in PLAIN layout; the 20-term dot uses fma.rn.f32x2 packed over the j dimension
// (float4 LDS gives aligned register pairs usable directly as {h_j,h_j+1} operands),
// finished with one horizontal add per output. No __syncthreads anywhere.
// Grid = 148 CTAs x 10 warps -> exactly 1 CTA per SM, balanced load.

#define B_TOTAL 4096
#define T_STEPS 2048
#define H_DIM   20
#define O_DIM   4
#define WARPS_CTA 10
#define CTA_THREADS (WARPS_CTA * 32)
#define GRID 148

typedef unsigned long long u64;

__device__ __forceinline__ u64 pack2(float lo, float hi) {
    u64 r; asm("mov.b64 %0, {%1,%2};" : "=l"(r) : "f"(lo), "f"(hi)); return r;
}
__device__ __forceinline__ void unpack2(u64 v, float& lo, float& hi) {
    asm("mov.b64 {%0,%1}, %2;" : "=f"(lo), "=f"(hi) : "l"(v));
}
__device__ __forceinline__ u64 fma2(u64 a, u64 b, u64 c) {
    u64 d; asm("fma.rn.f32x2 %0, %1, %2, %3;" : "=l"(d) : "l"(a), "l"(b), "l"(c)); return d;
}
__device__ __forceinline__ u64 add2(u64 a, u64 b) {
    u64 d; asm("add.rn.f32x2 %0, %1, %2;" : "=l"(d) : "l"(a), "l"(b)); return d;
}
__device__ __forceinline__ float ex2a(float x) {
    float r; asm("ex2.approx.f32 %0, %1;" : "=f"(r) : "f"(x)); return r;
}
__device__ __forceinline__ float rcpa(float x) {
    float r; asm("rcp.approx.f32 %0, %1;" : "=f"(r) : "f"(x)); return r;
}
__device__ __forceinline__ float tanh_acc(float x) {
    // tanh(x) = 1 - 2/(exp(2x)+1), via ex2.approx + rcp.approx (~1e-7 rel err)
    const float C = 2.8853900817779268f;   // 2*log2(e)
    float e = ex2a(x * C);
    float r = rcpa(e + 1.0f);
    return fmaf(r, -2.0f, 1.0f);
}

// One RNN step for one thread (batch g, outputs o0, o0+1).
// src/dst: this warp's ping-pong buffers (base of 64-word region).
__device__ __forceinline__ void rnn_step(
    const float* __restrict__ src, float* __restrict__ dst,
    int g, int o0, bool st, ulonglong2 xv,
    const u64* __restrict__ W0, const u64* __restrict__ W1,
    ulonglong2 Wi0, ulonglong2 Wi1, u64 seed0, u64 seed1)
{
    const ulonglong2* hsrc = reinterpret_cast<const ulonglong2*>(src + g * H_DIM);
    ulonglong2 hv0 = hsrc[0];   // {h0,h1},{h2,h3}
    ulonglong2 hv1 = hsrc[1];
    ulonglong2 hv2 = hsrc[2];
    ulonglong2 hv3 = hsrc[3];
    ulonglong2 hv4 = hsrc[4];

    // 4 independent f32x2 chains (2 per output) for ILP; depth ~6.
    u64 a0 = fma2(xv.x, Wi0.x, seed0);     // {x0*W+bias, x1*W}
    u64 b0 = fma2(xv.y, Wi0.y, pack2(0.f, 0.f));
    u64 a1 = fma2(xv.x, Wi1.x, seed1);
    u64 b1 = fma2(xv.y, Wi1.y, pack2(0.f, 0.f));

    a0 = fma2(hv0.x, W0[0], a0);  b0 = fma2(hv0.y, W0[1], b0);
    a1 = fma2(hv0.x, W1[0], a1);  b1 = fma2(hv0.y, W1[1], b1);
    a0 = fma2(hv1.x, W0[2], a0);  b0 = fma2(hv1.y, W0[3], b0);
    a1 = fma2(hv1.x, W1[2], a1);  b1 = fma2(hv1.y, W1[3], b1);
    a0 = fma2(hv2.x, W0[4], a0);  b0 = fma2(hv2.y, W0[5], b0);
    a1 = fma2(hv2.x, W1[4], a1);  b1 = fma2(hv2.y, W1[5], b1);
    a0 = fma2(hv3.x, W0[6], a0);  b0 = fma2(hv3.y, W0[7], b0);
    a1 = fma2(hv3.x, W1[6], a1);  b1 = fma2(hv3.y, W1[7], b1);
    a0 = fma2(hv4.x, W0[8], a0);  b0 = fma2(hv4.y, W0[9], b0);
    a1 = fma2(hv4.x, W1[8], a1);  b1 = fma2(hv4.y, W1[9], b1);

    u64 s0 = add2(a0, b0);
    u64 s1 = add2(a1, b1);

    float l0, h0f, l1, h1f;
    unpack2(s0, l0, h0f);
    unpack2(s1, l1, h1f);
    float t0 = tanh_acc(l0 + h0f);
    float t1 = tanh_acc(l1 + h1f);

    if (st) {
        *reinterpret_cast<u64*>(dst + g * H_DIM + o0) = pack2(t0, t1);
    }
    __syncwarp();
}

__global__ void __launch_bounds__(CTA_THREADS, 1)
rnn_tanh_kernel(
    const float* __restrict__ x,     const float* __restrict__ h0,
    const float* __restrict__ W_ih,  const float* __restrict__ W_hh,
    const float* __restrict__ b_ih,  const float* __restrict__ b_hh,
    const float* __restrict__ fc_w,  const float* __restrict__ fc_b,
    float* __restrict__ out)
{
    __shared__ __align__(128) float sm[WARPS_CTA][2][64];

    const int lane = threadIdx.x & 31;
    const int w    = threadIdx.x >> 5;
    const int gw   = blockIdx.x * WARPS_CTA + w;     // global warp id
    if (gw * 3 >= B_TOTAL) return;                   // whole warp idle

    const int  g  = (lane < 30) ? (lane / 10) : 2;   // batch within warp
    const int  p  = (lane < 30) ? (lane % 10) : (lane - 30);
    const bool st = (lane < 30);                     // this lane stores
    const int  b  = gw * 3 + g;
    const int  bc = (b < B_TOTAL) ? b : (B_TOTAL - 1);
    const int  o0 = 2 * p;                           // owned outputs o0, o0+1

    // ---- per-thread weights (packed over j) ----
    const u64* whh = reinterpret_cast<const u64*>(W_hh);   // row = 10 u64 pairs
    u64 W0[10], W1[10];
    #pragma unroll
    for (int q = 0; q < 10; q++) {
        W0[q] = __ldg(&whh[o0 * 10 + q]);
        W1[q] = __ldg(&whh[(o0 + 1) * 10 + q]);
    }
    const ulonglong2* wih = reinterpret_cast<const ulonglong2*>(W_ih);  // row = 16B
    ulonglong2 Wi0 = __ldg(&wih[o0]);
    ulonglong2 Wi1 = __ldg(&wih[o0 + 1]);
    const float bias0 = __ldg(&b_ih[o0])     + __ldg(&b_hh[o0]);
    const float bias1 = __ldg(&b_ih[o0 + 1]) + __ldg(&b_hh[o0 + 1]);
    const u64 seed0 = pack2(bias0, 0.f);
    const u64 seed1 = pack2(bias1, 0.f);

    float* bufA = &sm[w][0][0];
    float* bufB = &sm[w][1][0];

    // ---- init h (plain layout) into buffer A ----
    {
        const float2* h2 = reinterpret_cast<const float2*>(h0);
        float2 hv = __ldg(&h2[bc * (H_DIM / 2) + p]);
        if (st) *reinterpret_cast<u64*>(bufA + g * H_DIM + o0) = pack2(hv.x, hv.y);
    }
    __syncwarp();

    // x[b][t] is 4 floats = one ulonglong2
    const ulonglong2* xp = reinterpret_cast<const ulonglong2*>(x) + (size_t)bc * T_STEPS;
    ulonglong2 xv = __ldg(&xp[0]);

    for (int t = 0; t < T_STEPS; t += 2) {
        ulonglong2 xn1 = __ldg(&xp[t + 1]);
        rnn_step(bufA, bufB, g, o0, st, xv, W0, W1, Wi0, Wi1, seed0, seed1);
        ulonglong2 xn2 = __ldg(&xp[(t + 2 < T_STEPS) ? (t + 2) : (T_STEPS - 1)]);
        rnn_step(bufB, bufA, g, o0, st, xn1, W0, W1, Wi0, Wi1, seed0, seed1);
        xv = xn2;
    }

    // Final h is in bufA (T even). Linear head: lanes with p < 4 handle output p.
    if (st && p < O_DIM && b < B_TOTAL) {
        const float* hf = bufA + g * H_DIM;
        float acc = __ldg(&fc_b[p]);
        #pragma unroll
        for (int j = 0; j < H_DIM; j++)
            acc = fmaf(hf[j], __ldg(&fc_w[p * H_DIM + j]), acc);
        out[b * O_DIM + p] = acc;
    }
}

extern "C" void kernel_launch(void* const* d_in, const int* in_sizes, int n_in,
                              void* d_out, int out_size)
{
    const float* x    = (const float*)d_in[0];
    const float* h0   = (const float*)d_in[1];
    const float* W_ih = (const float*)d_in[2];
    const float* W_hh = (const float*)d_in[3];
    const float* b_ih = (const float*)d_in[4];
    const float* b_hh = (const float*)d_in[5];
    const float* fc_w = (const float*)d_in[6];
    const float* fc_b = (const float*)d_in[7];
    float* out = (float*)d_out;

    rnn_tanh_kernel<<<GRID, CTA_THREADS>>>(x, h0, W_ih, W_hh, b_ih, b_hh,
                                           fc_w, fc_b, out);
}